// round 1
// baseline (speedup 1.0000x reference)
#include <cuda_runtime.h>
#include <math.h>

#define T_TOKENS 8192
#define HIDDEN   5120
#define NQ       40
#define NKV      10
#define HD       128
#define QKV_N    7680   // (40 + 10 + 10) * 128
#define S_LEN    1024

// Scratch (device globals: no allocation allowed anywhere)
__device__ float g_qkv[(size_t)T_TOKENS * QKV_N];    // [T][60][128]
__device__ float g_obuf[(size_t)T_TOKENS * HIDDEN];  // [T][40][128]

// ---------------------------------------------------------------------------
// SGEMM: C[M,N] = A[M,K] @ B[K,N], all row-major fp32.
// 128x128 block tile, BK=16, 256 threads, 8x8 microtile per thread.
// Requires M%128==0, N%128==0, K%16==0 (true for all our shapes).
// ---------------------------------------------------------------------------
__global__ __launch_bounds__(256) void sgemm_kernel(
    const float* __restrict__ A, const float* __restrict__ B,
    float* __restrict__ C, int M, int N, int K)
{
    __shared__ float a_s[16][132];  // transposed A tile, padded
    __shared__ float b_s[16][128];

    const int tid = threadIdx.x;
    const int ty = tid >> 4;        // 0..15 -> output row group
    const int tx = tid & 15;        // 0..15 -> output col group
    const int bm = blockIdx.y * 128;
    const int bn = blockIdx.x * 128;

    float acc[8][8];
#pragma unroll
    for (int i = 0; i < 8; i++)
#pragma unroll
        for (int j = 0; j < 8; j++) acc[i][j] = 0.0f;

    const float* Ab = A + (size_t)bm * K;
    const float* Bb = B + bn;

    for (int k0 = 0; k0 < K; k0 += 16) {
        // Load A tile 128x16 (transpose into a_s[k][m])
#pragma unroll
        for (int i = tid; i < 512; i += 256) {
            int row = i >> 2;            // 0..127
            int kp  = (i & 3) << 2;      // 0,4,8,12
            float4 v = *(const float4*)(Ab + (size_t)row * K + k0 + kp);
            a_s[kp + 0][row] = v.x;
            a_s[kp + 1][row] = v.y;
            a_s[kp + 2][row] = v.z;
            a_s[kp + 3][row] = v.w;
        }
        // Load B tile 16x128
#pragma unroll
        for (int i = tid; i < 512; i += 256) {
            int row = i >> 5;            // 0..15
            int col = (i & 31) << 2;     // 0..124
            *(float4*)(&b_s[row][col]) =
                *(const float4*)(Bb + (size_t)(k0 + row) * N + col);
        }
        __syncthreads();

#pragma unroll
        for (int kk = 0; kk < 16; kk++) {
            float4 fa0 = *(const float4*)&a_s[kk][ty * 8];
            float4 fa1 = *(const float4*)&a_s[kk][ty * 8 + 4];
            float4 fb0 = *(const float4*)&b_s[kk][tx * 8];
            float4 fb1 = *(const float4*)&b_s[kk][tx * 8 + 4];
            float fa[8] = {fa0.x, fa0.y, fa0.z, fa0.w, fa1.x, fa1.y, fa1.z, fa1.w};
            float fb[8] = {fb0.x, fb0.y, fb0.z, fb0.w, fb1.x, fb1.y, fb1.z, fb1.w};
#pragma unroll
            for (int i = 0; i < 8; i++)
#pragma unroll
                for (int j = 0; j < 8; j++)
                    acc[i][j] += fa[i] * fb[j];
        }
        __syncthreads();
    }

#pragma unroll
    for (int i = 0; i < 8; i++) {
        float* Cr = C + (size_t)(bm + ty * 8 + i) * N + bn + tx * 8;
        float4 c0 = make_float4(acc[i][0], acc[i][1], acc[i][2], acc[i][3]);
        float4 c1 = make_float4(acc[i][4], acc[i][5], acc[i][6], acc[i][7]);
        *(float4*)(Cr)     = c0;
        *(float4*)(Cr + 4) = c1;
    }
}

// ---------------------------------------------------------------------------
// RoPE in-place on q (heads 0..39) and k (heads 40..49) of g_qkv.
// One thread per (t, head, i) pair, i in [0,64).
// ---------------------------------------------------------------------------
__global__ void rope_kernel(const int* __restrict__ positions)
{
    const int total = T_TOKENS * 50 * 64;
    int idx = blockIdx.x * blockDim.x + threadIdx.x;
    if (idx >= total) return;
    int i = idx & 63;
    int n = (idx >> 6) % 50;
    int t = idx / (50 * 64);

    // inv_freq = 10000^(-i/64) = exp(-i * ln(10000)/64)
    float inv = expf(-0.14391156831212787f * (float)i);
    float ang = (float)positions[t] * inv;
    float s, c;
    sincosf(ang, &s, &c);

    size_t base = (size_t)t * QKV_N + n * HD + i;
    float x1 = g_qkv[base];
    float x2 = g_qkv[base + 64];
    g_qkv[base]      = x1 * c - x2 * s;
    g_qkv[base + 64] = x2 * c + x1 * s;
}

// ---------------------------------------------------------------------------
// Flash attention: grid (qt=16, head=40, batch=8), 256 threads.
// Q tile 64x128, K/V tiles 64x128, online softmax, GQA: kv_head = head/4.
// Thread (ty,tx): score rows ty*4+i, score cols tx+16*j (interleaved to
// avoid the stride-128 smem bank pathologies); output rows ty*4+i,
// cols tx*8..tx*8+7.
// ---------------------------------------------------------------------------
__global__ __launch_bounds__(256) void attn_kernel()
{
    extern __shared__ float sm[];
    float* q_s = sm;                  // 64 x 132
    float* k_s = q_s + 64 * 132;      // 64 x 132
    float* v_s = k_s + 64 * 132;      // 64 x 128
    float* p_s = v_s + 64 * 128;      // 64 x 68

    const int qt   = blockIdx.x;
    const int head = blockIdx.y;
    const int b    = blockIdx.z;
    const int kvh  = head >> 2;
    const int tid  = threadIdx.x;
    const int ty   = tid >> 4;
    const int tx   = tid & 15;

    const size_t rowbase = (size_t)b * S_LEN * QKV_N;

    // Load Q tile
    {
        const float* qb = g_qkv + rowbase + (size_t)(qt * 64) * QKV_N + head * HD;
#pragma unroll
        for (int i = tid; i < 2048; i += 256) {
            int r = i >> 5, c = (i & 31) << 2;
            *(float4*)(q_s + r * 132 + c) = *(const float4*)(qb + (size_t)r * QKV_N + c);
        }
    }

    float m[4], l[4], o[4][8];
#pragma unroll
    for (int i = 0; i < 4; i++) {
        m[i] = -1e30f; l[i] = 0.0f;
#pragma unroll
        for (int c = 0; c < 8; c++) o[i][c] = 0.0f;
    }
    const float scale = 0.08838834764831843f;  // 1/sqrt(128)

    for (int kt = 0; kt <= qt; kt++) {
        __syncthreads();  // protect k_s/v_s/p_s reuse (and q_s on first iter)
        const float* kb = g_qkv + rowbase + (size_t)(kt * 64) * QKV_N + (NQ + kvh) * HD;
        const float* vb = g_qkv + rowbase + (size_t)(kt * 64) * QKV_N + (NQ + NKV + kvh) * HD;
#pragma unroll
        for (int i = tid; i < 2048; i += 256) {
            int r = i >> 5, c = (i & 31) << 2;
            *(float4*)(k_s + r * 132 + c) = *(const float4*)(kb + (size_t)r * QKV_N + c);
            *(float4*)(v_s + r * 128 + c) = *(const float4*)(vb + (size_t)r * QKV_N + c);
        }
        __syncthreads();

        // S = Q @ K^T for this tile
        float s[4][4];
#pragma unroll
        for (int i = 0; i < 4; i++)
#pragma unroll
            for (int j = 0; j < 4; j++) s[i][j] = 0.0f;

#pragma unroll 8
        for (int d = 0; d < 128; d += 4) {
            float4 qa[4], ka[4];
#pragma unroll
            for (int i = 0; i < 4; i++)
                qa[i] = *(const float4*)(q_s + (ty * 4 + i) * 132 + d);
#pragma unroll
            for (int j = 0; j < 4; j++)
                ka[j] = *(const float4*)(k_s + (tx + 16 * j) * 132 + d);
#pragma unroll
            for (int i = 0; i < 4; i++)
#pragma unroll
                for (int j = 0; j < 4; j++)
                    s[i][j] += qa[i].x * ka[j].x + qa[i].y * ka[j].y +
                               qa[i].z * ka[j].z + qa[i].w * ka[j].w;
        }

        // Mask + online softmax update
#pragma unroll
        for (int i = 0; i < 4; i++) {
            int grow = qt * 64 + ty * 4 + i;
            float mx = -1e30f;
#pragma unroll
            for (int j = 0; j < 4; j++) {
                int gcol = kt * 64 + tx + 16 * j;
                float val = (gcol <= grow) ? s[i][j] * scale : -1e30f;
                s[i][j] = val;
                mx = fmaxf(mx, val);
            }
#pragma unroll
            for (int off = 8; off >= 1; off >>= 1)
                mx = fmaxf(mx, __shfl_xor_sync(0xffffffffu, mx, off));
            float mnew  = fmaxf(m[i], mx);
            float alpha = __expf(m[i] - mnew);
            float rsum = 0.0f;
#pragma unroll
            for (int j = 0; j < 4; j++) {
                float p = __expf(s[i][j] - mnew);
                p_s[(ty * 4 + i) * 68 + tx + 16 * j] = p;
                rsum += p;
            }
#pragma unroll
            for (int off = 8; off >= 1; off >>= 1)
                rsum += __shfl_xor_sync(0xffffffffu, rsum, off);
            l[i] = l[i] * alpha + rsum;
            m[i] = mnew;
#pragma unroll
            for (int c = 0; c < 8; c++) o[i][c] *= alpha;
        }
        __syncthreads();

        // O += P @ V
#pragma unroll 8
        for (int kk = 0; kk < 64; kk++) {
            float4 vb0 = *(const float4*)(v_s + kk * 128 + tx * 8);
            float4 vb1 = *(const float4*)(v_s + kk * 128 + tx * 8 + 4);
#pragma unroll
            for (int i = 0; i < 4; i++) {
                float p = p_s[(ty * 4 + i) * 68 + kk];
                o[i][0] += p * vb0.x; o[i][1] += p * vb0.y;
                o[i][2] += p * vb0.z; o[i][3] += p * vb0.w;
                o[i][4] += p * vb1.x; o[i][5] += p * vb1.y;
                o[i][6] += p * vb1.z; o[i][7] += p * vb1.w;
            }
        }
    }

    // Write normalized output tile to g_obuf [T][40*128]
#pragma unroll
    for (int i = 0; i < 4; i++) {
        float inv = 1.0f / l[i];
        int t = b * S_LEN + qt * 64 + ty * 4 + i;
        float* ob = g_obuf + (size_t)t * HIDDEN + head * HD + tx * 8;
        float4 r0 = make_float4(o[i][0] * inv, o[i][1] * inv, o[i][2] * inv, o[i][3] * inv);
        float4 r1 = make_float4(o[i][4] * inv, o[i][5] * inv, o[i][6] * inv, o[i][7] * inv);
        *(float4*)(ob)     = r0;
        *(float4*)(ob + 4) = r1;
    }
}

// ---------------------------------------------------------------------------
extern "C" void kernel_launch(void* const* d_in, const int* in_sizes, int n_in,
                              void* d_out, int out_size)
{
    const float* x        = (const float*)d_in[0];  // [T, 5120]
    const float* w_qkv    = (const float*)d_in[1];  // [5120, 60, 128] -> [5120, 7680]
    const float* w_o      = (const float*)d_in[2];  // [40, 128, 5120] -> [5120, 5120]
    const int*   positions= (const int*)d_in[3];    // [T]
    float*       out      = (float*)d_out;          // [T, 5120]

    float* qkv  = nullptr;
    float* obuf = nullptr;
    cudaGetSymbolAddress((void**)&qkv,  g_qkv);
    cudaGetSymbolAddress((void**)&obuf, g_obuf);

    // 1) QKV projection
    {
        dim3 grid(QKV_N / 128, T_TOKENS / 128);
        sgemm_kernel<<<grid, 256>>>(x, w_qkv, qkv, T_TOKENS, QKV_N, HIDDEN);
    }

    // 2) RoPE on q and k in place
    {
        int total = T_TOKENS * 50 * 64;
        rope_kernel<<<(total + 255) / 256, 256>>>(positions);
    }

    // 3) Causal GQA flash attention
    {
        size_t smem = (size_t)(64 * 132 * 2 + 64 * 128 + 64 * 68) * sizeof(float);
        cudaFuncSetAttribute(attn_kernel,
                             cudaFuncAttributeMaxDynamicSharedMemorySize, (int)smem);
        dim3 grid(16, NQ, 8);
        attn_kernel<<<grid, 256, smem>>>();
    }

    // 4) Output projection
    {
        dim3 grid(HIDDEN / 128, T_TOKENS / 128);
        sgemm_kernel<<<grid, 256>>>(obuf, w_o, out, T_TOKENS, HIDDEN, HIDDEN);
    }
}

// round 3
// speedup vs baseline: 2.7104x; 2.7104x over previous
#include <cuda_runtime.h>
#include <cstdint>
#include <math.h>

#define T_TOKENS 8192
#define HIDDEN   5120
#define NQ       40
#define NKV      10
#define HD       128
#define QKV_N    7680
#define S_LEN    1024
#define KDIM     5120

// Scratch (device globals: no allocation allowed anywhere)
__device__ float g_qkv[(size_t)T_TOKENS * QKV_N];
__device__ float g_obuf[(size_t)T_TOKENS * HIDDEN];
__device__ float g_xr [(size_t)T_TOKENS * HIDDEN];   // tf32-rounded x
__device__ float g_wa [(size_t)HIDDEN * QKV_N];      // tf32-rounded w_qkv
__device__ float g_wb [(size_t)HIDDEN * HIDDEN];     // tf32-rounded w_o

// ===========================================================================
// helpers
// ===========================================================================
__device__ __forceinline__ uint32_t smem_u32(const void* p) {
    uint32_t a;
    asm("{ .reg .u64 t; cvta.to.shared.u64 t, %1; cvt.u32.u64 %0, t; }"
        : "=r"(a) : "l"(p));
    return a;
}

__device__ __forceinline__ uint32_t tf32r(float x) {
    uint32_t u;
    asm("cvt.rna.tf32.f32 %0, %1;" : "=r"(u) : "f"(x));
    return u;
}

__device__ __forceinline__ void cp_async16(uint32_t dst, const void* src) {
    asm volatile("cp.async.cg.shared.global [%0], [%1], 16;"
                 :: "r"(dst), "l"(src) : "memory");
}

__device__ __forceinline__ void ldsm_x4(uint32_t* r, uint32_t addr) {
    asm volatile("ldmatrix.sync.aligned.m8n8.x4.shared.b16 {%0,%1,%2,%3}, [%4];"
                 : "=r"(r[0]), "=r"(r[1]), "=r"(r[2]), "=r"(r[3]) : "r"(addr));
}

__device__ __forceinline__ void mma_tf32(float* d, const uint32_t* a,
                                         uint32_t b0, uint32_t b1) {
    asm volatile(
        "mma.sync.aligned.m16n8k8.row.col.f32.tf32.tf32.f32 "
        "{%0,%1,%2,%3}, {%4,%5,%6,%7}, {%8,%9}, {%0,%1,%2,%3};"
        : "+f"(d[0]), "+f"(d[1]), "+f"(d[2]), "+f"(d[3])
        : "r"(a[0]), "r"(a[1]), "r"(a[2]), "r"(a[3]), "r"(b0), "r"(b1));
}

// ===========================================================================
// tf32 -> rounded-copy kernel (RNA), float4 vectorized
// ===========================================================================
__global__ void cvt_tf32_kernel(const float4* __restrict__ src,
                                float4* __restrict__ dst, int n4)
{
    int i = blockIdx.x * blockDim.x + threadIdx.x;
    if (i >= n4) return;
    float4 v = src[i];
    float4 o;
    o.x = __uint_as_float(tf32r(v.x));
    o.y = __uint_as_float(tf32r(v.y));
    o.z = __uint_as_float(tf32r(v.z));
    o.w = __uint_as_float(tf32r(v.w));
    dst[i] = o;
}

// ===========================================================================
// TF32 mma.sync GEMM: C[M,N] = A[M,K] @ B[K,N], row-major, M%128==N%128==0,
// K%32==0. A,B must already be tf32-rounded (raw fp32 bits with low mantissa 0).
// Block 128x128, BK=32, 8 warps (2 x 4), warp tile 64x32.
// A smem: [m][36] floats (144B rows, 16B aligned), B smem: [k][132] floats.
// 2-stage cp.async pipeline.
// ===========================================================================
#define A_ST_B 18432             // 128 * 144
#define B_ST_B 16896             // 32 * 528
#define STAGE_B (A_ST_B + B_ST_B)
#define GEMM_SMEM (2 * STAGE_B)  // 70656

__global__ __launch_bounds__(256, 2)
void tc_gemm(const float* __restrict__ A, const float* __restrict__ B,
             float* __restrict__ C, int M, int N, int K)
{
    extern __shared__ __align__(16) char smem[];
    const uint32_t sbase = smem_u32(smem);
    const int tid  = threadIdx.x;
    const int lane = tid & 31;
    const int wid  = tid >> 5;
    const int wm   = wid & 1;        // 0..1  (64 rows each)
    const int wn   = wid >> 1;       // 0..3  (32 cols each)
    const int bm = blockIdx.y * 128, bn = blockIdx.x * 128;

    const float* Ag = A + (size_t)bm * K;
    const float* Bg = B + bn;

    float acc[4][4][4];
#pragma unroll
    for (int i = 0; i < 4; i++)
#pragma unroll
        for (int j = 0; j < 4; j++)
#pragma unroll
            for (int q = 0; q < 4; q++) acc[i][j][q] = 0.0f;

    // ---- async copy of chunk c into stage st ----
#define ISSUE_CHUNK(c, st) do {                                              \
        uint32_t a_dst = sbase + (st) * STAGE_B;                             \
        uint32_t b_dst = a_dst + A_ST_B;                                     \
        _Pragma("unroll")                                                    \
        for (int i = 0; i < 4; i++) {                                        \
            int idx = i * 256 + tid;                                         \
            int row = idx >> 3, kq = idx & 7;                                \
            cp_async16(a_dst + row * 144 + kq * 16,                          \
                       Ag + (size_t)row * K + (c) * 32 + kq * 4);            \
        }                                                                    \
        _Pragma("unroll")                                                    \
        for (int i = 0; i < 4; i++) {                                        \
            int idx = i * 256 + tid;                                         \
            int row = idx >> 5, nq = idx & 31;                               \
            cp_async16(b_dst + row * 528 + nq * 16,                          \
                       Bg + (size_t)((c) * 32 + row) * N + nq * 4);          \
        }                                                                    \
        asm volatile("cp.async.commit_group;" ::: "memory");                 \
    } while (0)

    ISSUE_CHUNK(0, 0);

    // per-thread ldmatrix base for A fragments
    const uint32_t a_tbase = sbase
        + (uint32_t)((wm * 64 + ((lane >> 3) & 1) * 8 + (lane & 7)) * 144)
        + (uint32_t)((lane >> 4) * 16);
    const int brow = lane & 3;
    const int bcol = wn * 32 + (lane >> 2);

    const int NCH = K / 32;
    for (int c = 0; c < NCH; c++) {
        const int st = c & 1;
        if (c + 1 < NCH) {
            ISSUE_CHUNK(c + 1, st ^ 1);
            asm volatile("cp.async.wait_group 1;" ::: "memory");
        } else {
            asm volatile("cp.async.wait_group 0;" ::: "memory");
        }
        __syncthreads();

        const uint32_t a_base = a_tbase + st * STAGE_B;
        const float* Bs = (const float*)(smem + st * STAGE_B + A_ST_B);

#pragma unroll
        for (int j = 0; j < 4; j++) {
            uint32_t afr[4][4];
#pragma unroll
            for (int mt = 0; mt < 4; mt++)
                ldsm_x4(afr[mt], a_base + mt * 2304 + j * 32);

            uint32_t b0[4], b1[4];
#pragma unroll
            for (int nt = 0; nt < 4; nt++) {
                b0[nt] = __float_as_uint(Bs[(8 * j + brow) * 132 + bcol + nt * 8]);
                b1[nt] = __float_as_uint(Bs[(8 * j + 4 + brow) * 132 + bcol + nt * 8]);
            }
#pragma unroll
            for (int mt = 0; mt < 4; mt++)
#pragma unroll
                for (int nt = 0; nt < 4; nt++)
                    mma_tf32(acc[mt][nt], afr[mt], b0[nt], b1[nt]);
        }
        __syncthreads();
    }

    // Epilogue: c0/c1 at (row, 2c),(row,2c+1); c2/c3 at row+8
    const int erow = bm + wm * 64 + (lane >> 2);
    const int ecol = bn + wn * 32 + 2 * (lane & 3);
#pragma unroll
    for (int mt = 0; mt < 4; mt++) {
#pragma unroll
        for (int nt = 0; nt < 4; nt++) {
            float* p0 = C + (size_t)(erow + mt * 16) * N + ecol + nt * 8;
            float* p1 = p0 + 8 * N;
            *(float2*)p0 = make_float2(acc[mt][nt][0], acc[mt][nt][1]);
            *(float2*)p1 = make_float2(acc[mt][nt][2], acc[mt][nt][3]);
        }
    }
#undef ISSUE_CHUNK
}

// ===========================================================================
// RoPE in-place on q (heads 0..39) and k (heads 40..49) of g_qkv.
// ===========================================================================
__global__ void rope_kernel(const int* __restrict__ positions)
{
    const int total = T_TOKENS * 50 * 64;
    int idx = blockIdx.x * blockDim.x + threadIdx.x;
    if (idx >= total) return;
    int i = idx & 63;
    int n = (idx >> 6) % 50;
    int t = idx / (50 * 64);

    float inv = expf(-0.14391156831212787f * (float)i);
    float ang = (float)positions[t] * inv;
    float s, c;
    sincosf(ang, &s, &c);

    size_t base = (size_t)t * QKV_N + n * HD + i;
    float x1 = g_qkv[base];
    float x2 = g_qkv[base + 64];
    g_qkv[base]      = x1 * c - x2 * s;
    g_qkv[base + 64] = x2 * c + x1 * s;
}

// ===========================================================================
// Flash attention (fp32) — output stored tf32-rounded for the o-proj GEMM.
// ===========================================================================
__global__ __launch_bounds__(256) void attn_kernel()
{
    extern __shared__ float sm[];
    float* q_s = sm;                  // 64 x 132
    float* k_s = q_s + 64 * 132;      // 64 x 132
    float* v_s = k_s + 64 * 132;      // 64 x 128
    float* p_s = v_s + 64 * 128;      // 64 x 68

    const int qt   = blockIdx.x;
    const int head = blockIdx.y;
    const int b    = blockIdx.z;
    const int kvh  = head >> 2;
    const int tid  = threadIdx.x;
    const int ty   = tid >> 4;
    const int tx   = tid & 15;

    const size_t rowbase = (size_t)b * S_LEN * QKV_N;

    {
        const float* qb = g_qkv + rowbase + (size_t)(qt * 64) * QKV_N + head * HD;
#pragma unroll
        for (int i = tid; i < 2048; i += 256) {
            int r = i >> 5, c = (i & 31) << 2;
            *(float4*)(q_s + r * 132 + c) = *(const float4*)(qb + (size_t)r * QKV_N + c);
        }
    }

    float m[4], l[4], o[4][8];
#pragma unroll
    for (int i = 0; i < 4; i++) {
        m[i] = -1e30f; l[i] = 0.0f;
#pragma unroll
        for (int c = 0; c < 8; c++) o[i][c] = 0.0f;
    }
    const float scale = 0.08838834764831843f;

    for (int kt = 0; kt <= qt; kt++) {
        __syncthreads();
        const float* kb = g_qkv + rowbase + (size_t)(kt * 64) * QKV_N + (NQ + kvh) * HD;
        const float* vb = g_qkv + rowbase + (size_t)(kt * 64) * QKV_N + (NQ + NKV + kvh) * HD;
#pragma unroll
        for (int i = tid; i < 2048; i += 256) {
            int r = i >> 5, c = (i & 31) << 2;
            *(float4*)(k_s + r * 132 + c) = *(const float4*)(kb + (size_t)r * QKV_N + c);
            *(float4*)(v_s + r * 128 + c) = *(const float4*)(vb + (size_t)r * QKV_N + c);
        }
        __syncthreads();

        float s[4][4];
#pragma unroll
        for (int i = 0; i < 4; i++)
#pragma unroll
            for (int j = 0; j < 4; j++) s[i][j] = 0.0f;

#pragma unroll 8
        for (int d = 0; d < 128; d += 4) {
            float4 qa[4], ka[4];
#pragma unroll
            for (int i = 0; i < 4; i++)
                qa[i] = *(const float4*)(q_s + (ty * 4 + i) * 132 + d);
#pragma unroll
            for (int j = 0; j < 4; j++)
                ka[j] = *(const float4*)(k_s + (tx + 16 * j) * 132 + d);
#pragma unroll
            for (int i = 0; i < 4; i++)
#pragma unroll
                for (int j = 0; j < 4; j++)
                    s[i][j] += qa[i].x * ka[j].x + qa[i].y * ka[j].y +
                               qa[i].z * ka[j].z + qa[i].w * ka[j].w;
        }

#pragma unroll
        for (int i = 0; i < 4; i++) {
            int grow = qt * 64 + ty * 4 + i;
            float mx = -1e30f;
#pragma unroll
            for (int j = 0; j < 4; j++) {
                int gcol = kt * 64 + tx + 16 * j;
                float val = (gcol <= grow) ? s[i][j] * scale : -1e30f;
                s[i][j] = val;
                mx = fmaxf(mx, val);
            }
#pragma unroll
            for (int off = 8; off >= 1; off >>= 1)
                mx = fmaxf(mx, __shfl_xor_sync(0xffffffffu, mx, off));
            float mnew  = fmaxf(m[i], mx);
            float alpha = __expf(m[i] - mnew);
            float rsum = 0.0f;
#pragma unroll
            for (int j = 0; j < 4; j++) {
                float p = __expf(s[i][j] - mnew);
                p_s[(ty * 4 + i) * 68 + tx + 16 * j] = p;
                rsum += p;
            }
#pragma unroll
            for (int off = 8; off >= 1; off >>= 1)
                rsum += __shfl_xor_sync(0xffffffffu, rsum, off);
            l[i] = l[i] * alpha + rsum;
            m[i] = mnew;
#pragma unroll
            for (int c = 0; c < 8; c++) o[i][c] *= alpha;
        }
        __syncthreads();

#pragma unroll 8
        for (int kk = 0; kk < 64; kk++) {
            float4 vb0 = *(const float4*)(v_s + kk * 128 + tx * 8);
            float4 vb1 = *(const float4*)(v_s + kk * 128 + tx * 8 + 4);
#pragma unroll
            for (int i = 0; i < 4; i++) {
                float p = p_s[(ty * 4 + i) * 68 + kk];
                o[i][0] += p * vb0.x; o[i][1] += p * vb0.y;
                o[i][2] += p * vb0.z; o[i][3] += p * vb0.w;
                o[i][4] += p * vb1.x; o[i][5] += p * vb1.y;
                o[i][6] += p * vb1.z; o[i][7] += p * vb1.w;
            }
        }
    }

#pragma unroll
    for (int i = 0; i < 4; i++) {
        float inv = 1.0f / l[i];
        int t = b * S_LEN + qt * 64 + ty * 4 + i;
        float* ob = g_obuf + (size_t)t * HIDDEN + head * HD + tx * 8;
        // pre-round to tf32 (RNA) so the o-proj GEMM sees clean tf32 inputs
        float4 r0 = make_float4(
            __uint_as_float(tf32r(o[i][0] * inv)),
            __uint_as_float(tf32r(o[i][1] * inv)),
            __uint_as_float(tf32r(o[i][2] * inv)),
            __uint_as_float(tf32r(o[i][3] * inv)));
        float4 r1 = make_float4(
            __uint_as_float(tf32r(o[i][4] * inv)),
            __uint_as_float(tf32r(o[i][5] * inv)),
            __uint_as_float(tf32r(o[i][6] * inv)),
            __uint_as_float(tf32r(o[i][7] * inv)));
        *(float4*)(ob)     = r0;
        *(float4*)(ob + 4) = r1;
    }
}

// ===========================================================================
extern "C" void kernel_launch(void* const* d_in, const int* in_sizes, int n_in,
                              void* d_out, int out_size)
{
    const float* x         = (const float*)d_in[0];  // [T, 5120]
    const float* w_qkv     = (const float*)d_in[1];  // [5120, 7680]
    const float* w_o       = (const float*)d_in[2];  // [5120, 5120]
    const int*   positions = (const int*)d_in[3];    // [T]
    float*       out       = (float*)d_out;          // [T, 5120]

    float *qkv, *obuf, *xr, *wa, *wb;
    cudaGetSymbolAddress((void**)&qkv,  g_qkv);
    cudaGetSymbolAddress((void**)&obuf, g_obuf);
    cudaGetSymbolAddress((void**)&xr,   g_xr);
    cudaGetSymbolAddress((void**)&wa,   g_wa);
    cudaGetSymbolAddress((void**)&wb,   g_wb);

    cudaFuncSetAttribute(tc_gemm, cudaFuncAttributeMaxDynamicSharedMemorySize,
                         GEMM_SMEM);

    // 0) tf32-RNA pre-rounding of GEMM inputs
    {
        int n4x = (T_TOKENS * HIDDEN) / 4;
        cvt_tf32_kernel<<<(n4x + 255) / 256, 256>>>((const float4*)x, (float4*)xr, n4x);
        int n4a = (HIDDEN * QKV_N) / 4;
        cvt_tf32_kernel<<<(n4a + 255) / 256, 256>>>((const float4*)w_qkv, (float4*)wa, n4a);
        int n4b = (HIDDEN * HIDDEN) / 4;
        cvt_tf32_kernel<<<(n4b + 255) / 256, 256>>>((const float4*)w_o, (float4*)wb, n4b);
    }

    // 1) QKV projection (tf32 mma.sync)
    {
        dim3 grid(QKV_N / 128, T_TOKENS / 128);
        tc_gemm<<<grid, 256, GEMM_SMEM>>>(xr, wa, qkv, T_TOKENS, QKV_N, KDIM);
    }

    // 2) RoPE
    {
        int total = T_TOKENS * 50 * 64;
        rope_kernel<<<(total + 255) / 256, 256>>>(positions);
    }

    // 3) Causal GQA flash attention (fp32)
    {
        size_t smem = (size_t)(64 * 132 * 2 + 64 * 128 + 64 * 68) * sizeof(float);
        cudaFuncSetAttribute(attn_kernel,
                             cudaFuncAttributeMaxDynamicSharedMemorySize, (int)smem);
        dim3 grid(16, NQ, 8);
        attn_kernel<<<grid, 256, smem>>>();
    }

    // 4) Output projection (tf32 mma.sync)
    {
        dim3 grid(HIDDEN / 128, T_TOKENS / 128);
        tc_gemm<<<grid, 256, GEMM_SMEM>>>(obuf, wb, out, T_TOKENS, HIDDEN, KDIM);
    }
}

// round 4
// speedup vs baseline: 2.9438x; 1.0861x over previous
#include <cuda_runtime.h>
#include <cstdint>
#include <math.h>

#define T_TOKENS 8192
#define HIDDEN   5120
#define NQ       40
#define NKV      10
#define HD       128
#define QKV_N    7680
#define S_LEN    1024
#define KDIM     5120

// Scratch (device globals: no allocation allowed anywhere)
__device__ float g_qkv[(size_t)T_TOKENS * QKV_N];
__device__ float g_obuf[(size_t)T_TOKENS * HIDDEN];
__device__ float g_xr [(size_t)T_TOKENS * HIDDEN];   // tf32-rounded x
__device__ float g_wa [(size_t)HIDDEN * QKV_N];      // tf32-rounded w_qkv^T [7680][5120]
__device__ float g_wb [(size_t)HIDDEN * HIDDEN];     // tf32-rounded w_o^T   [5120][5120]

// ===========================================================================
// helpers
// ===========================================================================
__device__ __forceinline__ uint32_t smem_u32(const void* p) {
    uint32_t a;
    asm("{ .reg .u64 t; cvta.to.shared.u64 t, %1; cvt.u32.u64 %0, t; }"
        : "=r"(a) : "l"(p));
    return a;
}

__device__ __forceinline__ uint32_t tf32r(float x) {
    uint32_t u;
    asm("cvt.rna.tf32.f32 %0, %1;" : "=r"(u) : "f"(x));
    return u;
}

__device__ __forceinline__ void cp_async16(uint32_t dst, const void* src) {
    asm volatile("cp.async.cg.shared.global [%0], [%1], 16;"
                 :: "r"(dst), "l"(src) : "memory");
}

__device__ __forceinline__ void ldsm_x4(uint32_t* r, uint32_t addr) {
    asm volatile("ldmatrix.sync.aligned.m8n8.x4.shared.b16 {%0,%1,%2,%3}, [%4];"
                 : "=r"(r[0]), "=r"(r[1]), "=r"(r[2]), "=r"(r[3]) : "r"(addr));
}

__device__ __forceinline__ void mma_tf32(float* d, const uint32_t* a,
                                         uint32_t b0, uint32_t b1) {
    asm volatile(
        "mma.sync.aligned.m16n8k8.row.col.f32.tf32.tf32.f32 "
        "{%0,%1,%2,%3}, {%4,%5,%6,%7}, {%8,%9}, {%0,%1,%2,%3};"
        : "+f"(d[0]), "+f"(d[1]), "+f"(d[2]), "+f"(d[3])
        : "r"(a[0]), "r"(a[1]), "r"(a[2]), "r"(a[3]), "r"(b0), "r"(b1));
}

// ===========================================================================
// tf32 rounded copy (no transpose) — for x
// ===========================================================================
__global__ void cvt_tf32_kernel(const float4* __restrict__ src,
                                float4* __restrict__ dst, int n4)
{
    int i = blockIdx.x * blockDim.x + threadIdx.x;
    if (i >= n4) return;
    float4 v = src[i];
    float4 o;
    o.x = __uint_as_float(tf32r(v.x));
    o.y = __uint_as_float(tf32r(v.y));
    o.z = __uint_as_float(tf32r(v.z));
    o.w = __uint_as_float(tf32r(v.w));
    dst[i] = o;
}

// ===========================================================================
// tf32 rounded transpose: src [R][C] -> dst [C][R]. R,C % 32 == 0.
// grid (C/32, R/32), block (32, 8)
// ===========================================================================
__global__ void transpose_tf32_kernel(const float* __restrict__ src,
                                      float* __restrict__ dst, int R, int C)
{
    __shared__ float tile[32][33];
    int bc = blockIdx.x * 32, br = blockIdx.y * 32;
    int tx = threadIdx.x, ty = threadIdx.y;
#pragma unroll
    for (int i = 0; i < 32; i += 8) {
        float v = src[(size_t)(br + ty + i) * C + bc + tx];
        tile[ty + i][tx] = __uint_as_float(tf32r(v));
    }
    __syncthreads();
#pragma unroll
    for (int i = 0; i < 32; i += 8)
        dst[(size_t)(bc + ty + i) * R + br + tx] = tile[tx][ty + i];
}

// ===========================================================================
// TF32 mma.sync GEMM: C[M,N] = A[M,K] @ Bt[N,K]^T, all row-major storage.
// A and Bt must already be tf32-rounded. Block 128x128, BK=32, 8 warps
// (2 x 4), warp tile 64x32. Both A and Bt staged K-major in smem with
// 144-byte row pitch; ALL fragments via ldmatrix (conflict-free).
// 2-stage cp.async pipeline, one __syncthreads per chunk.
// ===========================================================================
#define A_ST_B 18432             // 128 rows * 144 B
#define B_ST_B 18432             // 128 rows * 144 B
#define STAGE_B (A_ST_B + B_ST_B)
#define GEMM_SMEM (2 * STAGE_B)  // 73728

__global__ __launch_bounds__(256, 2)
void tc_gemm(const float* __restrict__ A, const float* __restrict__ Bt,
             float* __restrict__ C, int M, int N, int K)
{
    extern __shared__ __align__(16) char smem[];
    const uint32_t sbase = smem_u32(smem);
    const int tid  = threadIdx.x;
    const int lane = tid & 31;
    const int wid  = tid >> 5;
    const int wm   = wid & 1;        // 0..1  (64 rows each)
    const int wn   = wid >> 1;       // 0..3  (32 cols each)
    const int bm = blockIdx.y * 128, bn = blockIdx.x * 128;

    const float* Ag = A  + (size_t)bm * K;
    const float* Bg = Bt + (size_t)bn * K;

    float acc[4][4][4];
#pragma unroll
    for (int i = 0; i < 4; i++)
#pragma unroll
        for (int j = 0; j < 4; j++)
#pragma unroll
            for (int q = 0; q < 4; q++) acc[i][j][q] = 0.0f;

    // ---- async copy of chunk c into stage st (A and B identical pattern) ----
#define ISSUE_CHUNK(c, st) do {                                              \
        uint32_t a_dst = sbase + (st) * STAGE_B;                             \
        uint32_t b_dst = a_dst + A_ST_B;                                     \
        _Pragma("unroll")                                                    \
        for (int i = 0; i < 4; i++) {                                        \
            int idx = i * 256 + tid;                                         \
            int row = idx >> 3, kq = idx & 7;                                \
            cp_async16(a_dst + row * 144 + kq * 16,                          \
                       Ag + (size_t)row * K + (c) * 32 + kq * 4);            \
            cp_async16(b_dst + row * 144 + kq * 16,                          \
                       Bg + (size_t)row * K + (c) * 32 + kq * 4);            \
        }                                                                    \
        asm volatile("cp.async.commit_group;" ::: "memory");                 \
    } while (0)

    ISSUE_CHUNK(0, 0);

    // per-thread ldmatrix bases
    // A: lanes 0-7 rows r0..r7 (k-quad 0), 8-15 rows r8..r15, 16-31 same rows +16B
    const uint32_t a_tbase = sbase
        + (uint32_t)((wm * 64 + ((lane >> 3) & 1) * 8 + (lane & 7)) * 144)
        + (uint32_t)((lane >> 4) * 16);
    // B: lanes 0-7 n-rows 0..7 (k-quad 0), 8-15 same rows k-quad 1,
    //    16-23 n-rows 8..15 quad 0, 24-31 rows 8..15 quad 1
    const uint32_t b_tbase = sbase + A_ST_B
        + (uint32_t)((wn * 32 + (lane & 7) + ((lane >> 4) << 3)) * 144)
        + (uint32_t)(((lane >> 3) & 1) * 16);

    const int NCH = K / 32;
    for (int c = 0; c < NCH; c++) {
        const int st = c & 1;
        asm volatile("cp.async.wait_group 0;" ::: "memory");
        __syncthreads();
        if (c + 1 < NCH) ISSUE_CHUNK(c + 1, st ^ 1);

        const uint32_t a_base = a_tbase + st * STAGE_B;
        const uint32_t b_base = b_tbase + st * STAGE_B;

#pragma unroll
        for (int j = 0; j < 4; j++) {
            uint32_t afr[4][4];
#pragma unroll
            for (int mt = 0; mt < 4; mt++)
                ldsm_x4(afr[mt], a_base + mt * 2304 + j * 32);   // 2304 = 16*144

            uint32_t bfr[2][4];
#pragma unroll
            for (int p = 0; p < 2; p++)
                ldsm_x4(bfr[p], b_base + p * 2304 + j * 32);

#pragma unroll
            for (int mt = 0; mt < 4; mt++)
#pragma unroll
                for (int nt = 0; nt < 4; nt++)
                    mma_tf32(acc[mt][nt], afr[mt],
                             bfr[nt >> 1][(nt & 1) * 2],
                             bfr[nt >> 1][(nt & 1) * 2 + 1]);
        }
    }

    // Epilogue
    const int erow = bm + wm * 64 + (lane >> 2);
    const int ecol = bn + wn * 32 + 2 * (lane & 3);
#pragma unroll
    for (int mt = 0; mt < 4; mt++) {
#pragma unroll
        for (int nt = 0; nt < 4; nt++) {
            float* p0 = C + (size_t)(erow + mt * 16) * N + ecol + nt * 8;
            float* p1 = p0 + 8 * N;
            *(float2*)p0 = make_float2(acc[mt][nt][0], acc[mt][nt][1]);
            *(float2*)p1 = make_float2(acc[mt][nt][2], acc[mt][nt][3]);
        }
    }
#undef ISSUE_CHUNK
}

// ===========================================================================
// RoPE in-place on q (heads 0..39) and k (heads 40..49) of g_qkv.
// ===========================================================================
__global__ void rope_kernel(const int* __restrict__ positions)
{
    const int total = T_TOKENS * 50 * 64;
    int idx = blockIdx.x * blockDim.x + threadIdx.x;
    if (idx >= total) return;
    int i = idx & 63;
    int n = (idx >> 6) % 50;
    int t = idx / (50 * 64);

    float inv = expf(-0.14391156831212787f * (float)i);
    float ang = (float)positions[t] * inv;
    float s, c;
    sincosf(ang, &s, &c);

    size_t base = (size_t)t * QKV_N + n * HD + i;
    float x1 = g_qkv[base];
    float x2 = g_qkv[base + 64];
    g_qkv[base]      = x1 * c - x2 * s;
    g_qkv[base + 64] = x2 * c + x1 * s;
}

// ===========================================================================
// Flash attention (fp32) — output stored tf32-rounded for the o-proj GEMM.
// ===========================================================================
__global__ __launch_bounds__(256) void attn_kernel()
{
    extern __shared__ float sm[];
    float* q_s = sm;                  // 64 x 132
    float* k_s = q_s + 64 * 132;      // 64 x 132
    float* v_s = k_s + 64 * 132;      // 64 x 128
    float* p_s = v_s + 64 * 128;      // 64 x 68

    const int qt   = blockIdx.x;
    const int head = blockIdx.y;
    const int b    = blockIdx.z;
    const int kvh  = head >> 2;
    const int tid  = threadIdx.x;
    const int ty   = tid >> 4;
    const int tx   = tid & 15;

    const size_t rowbase = (size_t)b * S_LEN * QKV_N;

    {
        const float* qb = g_qkv + rowbase + (size_t)(qt * 64) * QKV_N + head * HD;
#pragma unroll
        for (int i = tid; i < 2048; i += 256) {
            int r = i >> 5, c = (i & 31) << 2;
            *(float4*)(q_s + r * 132 + c) = *(const float4*)(qb + (size_t)r * QKV_N + c);
        }
    }

    float m[4], l[4], o[4][8];
#pragma unroll
    for (int i = 0; i < 4; i++) {
        m[i] = -1e30f; l[i] = 0.0f;
#pragma unroll
        for (int c = 0; c < 8; c++) o[i][c] = 0.0f;
    }
    const float scale = 0.08838834764831843f;

    for (int kt = 0; kt <= qt; kt++) {
        __syncthreads();
        const float* kb = g_qkv + rowbase + (size_t)(kt * 64) * QKV_N + (NQ + kvh) * HD;
        const float* vb = g_qkv + rowbase + (size_t)(kt * 64) * QKV_N + (NQ + NKV + kvh) * HD;
#pragma unroll
        for (int i = tid; i < 2048; i += 256) {
            int r = i >> 5, c = (i & 31) << 2;
            *(float4*)(k_s + r * 132 + c) = *(const float4*)(kb + (size_t)r * QKV_N + c);
            *(float4*)(v_s + r * 128 + c) = *(const float4*)(vb + (size_t)r * QKV_N + c);
        }
        __syncthreads();

        float s[4][4];
#pragma unroll
        for (int i = 0; i < 4; i++)
#pragma unroll
            for (int j = 0; j < 4; j++) s[i][j] = 0.0f;

#pragma unroll 8
        for (int d = 0; d < 128; d += 4) {
            float4 qa[4], ka[4];
#pragma unroll
            for (int i = 0; i < 4; i++)
                qa[i] = *(const float4*)(q_s + (ty * 4 + i) * 132 + d);
#pragma unroll
            for (int j = 0; j < 4; j++)
                ka[j] = *(const float4*)(k_s + (tx + 16 * j) * 132 + d);
#pragma unroll
            for (int i = 0; i < 4; i++)
#pragma unroll
                for (int j = 0; j < 4; j++)
                    s[i][j] += qa[i].x * ka[j].x + qa[i].y * ka[j].y +
                               qa[i].z * ka[j].z + qa[i].w * ka[j].w;
        }

#pragma unroll
        for (int i = 0; i < 4; i++) {
            int grow = qt * 64 + ty * 4 + i;
            float mx = -1e30f;
#pragma unroll
            for (int j = 0; j < 4; j++) {
                int gcol = kt * 64 + tx + 16 * j;
                float val = (gcol <= grow) ? s[i][j] * scale : -1e30f;
                s[i][j] = val;
                mx = fmaxf(mx, val);
            }
#pragma unroll
            for (int off = 8; off >= 1; off >>= 1)
                mx = fmaxf(mx, __shfl_xor_sync(0xffffffffu, mx, off));
            float mnew  = fmaxf(m[i], mx);
            float alpha = __expf(m[i] - mnew);
            float rsum = 0.0f;
#pragma unroll
            for (int j = 0; j < 4; j++) {
                float p = __expf(s[i][j] - mnew);
                p_s[(ty * 4 + i) * 68 + tx + 16 * j] = p;
                rsum += p;
            }
#pragma unroll
            for (int off = 8; off >= 1; off >>= 1)
                rsum += __shfl_xor_sync(0xffffffffu, rsum, off);
            l[i] = l[i] * alpha + rsum;
            m[i] = mnew;
#pragma unroll
            for (int c = 0; c < 8; c++) o[i][c] *= alpha;
        }
        __syncthreads();

#pragma unroll 8
        for (int kk = 0; kk < 64; kk++) {
            float4 vb0 = *(const float4*)(v_s + kk * 128 + tx * 8);
            float4 vb1 = *(const float4*)(v_s + kk * 128 + tx * 8 + 4);
#pragma unroll
            for (int i = 0; i < 4; i++) {
                float p = p_s[(ty * 4 + i) * 68 + kk];
                o[i][0] += p * vb0.x; o[i][1] += p * vb0.y;
                o[i][2] += p * vb0.z; o[i][3] += p * vb0.w;
                o[i][4] += p * vb1.x; o[i][5] += p * vb1.y;
                o[i][6] += p * vb1.z; o[i][7] += p * vb1.w;
            }
        }
    }

#pragma unroll
    for (int i = 0; i < 4; i++) {
        float inv = 1.0f / l[i];
        int t = b * S_LEN + qt * 64 + ty * 4 + i;
        float* ob = g_obuf + (size_t)t * HIDDEN + head * HD + tx * 8;
        float4 r0 = make_float4(
            __uint_as_float(tf32r(o[i][0] * inv)),
            __uint_as_float(tf32r(o[i][1] * inv)),
            __uint_as_float(tf32r(o[i][2] * inv)),
            __uint_as_float(tf32r(o[i][3] * inv)));
        float4 r1 = make_float4(
            __uint_as_float(tf32r(o[i][4] * inv)),
            __uint_as_float(tf32r(o[i][5] * inv)),
            __uint_as_float(tf32r(o[i][6] * inv)),
            __uint_as_float(tf32r(o[i][7] * inv)));
        *(float4*)(ob)     = r0;
        *(float4*)(ob + 4) = r1;
    }
}

// ===========================================================================
extern "C" void kernel_launch(void* const* d_in, const int* in_sizes, int n_in,
                              void* d_out, int out_size)
{
    const float* x         = (const float*)d_in[0];  // [T, 5120]
    const float* w_qkv     = (const float*)d_in[1];  // [5120, 7680]
    const float* w_o       = (const float*)d_in[2];  // [5120, 5120]
    const int*   positions = (const int*)d_in[3];    // [T]
    float*       out       = (float*)d_out;          // [T, 5120]

    float *qkv, *obuf, *xr, *wa, *wb;
    cudaGetSymbolAddress((void**)&qkv,  g_qkv);
    cudaGetSymbolAddress((void**)&obuf, g_obuf);
    cudaGetSymbolAddress((void**)&xr,   g_xr);
    cudaGetSymbolAddress((void**)&wa,   g_wa);
    cudaGetSymbolAddress((void**)&wb,   g_wb);

    cudaFuncSetAttribute(tc_gemm, cudaFuncAttributeMaxDynamicSharedMemorySize,
                         GEMM_SMEM);

    // 0) tf32-RNA pre-rounding: x copy; weights transposed to [N][K]
    {
        int n4x = (T_TOKENS * HIDDEN) / 4;
        cvt_tf32_kernel<<<(n4x + 255) / 256, 256>>>((const float4*)x, (float4*)xr, n4x);
        dim3 blk(32, 8);
        transpose_tf32_kernel<<<dim3(QKV_N / 32, HIDDEN / 32), blk>>>(w_qkv, wa, HIDDEN, QKV_N);
        transpose_tf32_kernel<<<dim3(HIDDEN / 32, HIDDEN / 32), blk>>>(w_o, wb, HIDDEN, HIDDEN);
    }

    // 1) QKV projection (tf32 mma.sync, B transposed)
    {
        dim3 grid(QKV_N / 128, T_TOKENS / 128);
        tc_gemm<<<grid, 256, GEMM_SMEM>>>(xr, wa, qkv, T_TOKENS, QKV_N, KDIM);
    }

    // 2) RoPE
    {
        int total = T_TOKENS * 50 * 64;
        rope_kernel<<<(total + 255) / 256, 256>>>(positions);
    }

    // 3) Causal GQA flash attention (fp32)
    {
        size_t smem = (size_t)(64 * 132 * 2 + 64 * 128 + 64 * 68) * sizeof(float);
        cudaFuncSetAttribute(attn_kernel,
                             cudaFuncAttributeMaxDynamicSharedMemorySize, (int)smem);
        dim3 grid(16, NQ, 8);
        attn_kernel<<<grid, 256, smem>>>();
    }

    // 4) Output projection (tf32 mma.sync, B transposed)
    {
        dim3 grid(HIDDEN / 128, T_TOKENS / 128);
        tc_gemm<<<grid, 256, GEMM_SMEM>>>(obuf, wb, out, T_TOKENS, HIDDEN, KDIM);
    }
}